// round 10
// baseline (speedup 1.0000x reference)
#include <cuda_runtime.h>
#include <cuda_bf16.h>
#include <math.h>
#include <stdint.h>

// Problem constants: N=100000, D=128, C=1024, NUM_NODES=1e6.
#define MAX_N     100000
#define MAX_NODES 1000000
#define NCB       8            // C / BN column blocks

// Device scratch (no allocs allowed). NO 64-bit atomics (sm_103a trap).
__device__ unsigned long long g_cand[(size_t)(MAX_N + 128) * NCB];
__device__ int   g_winner[MAX_NODES];
__device__ float g_rn[MAX_N];
__device__ float g_cn[2048];
// int8 limb planes: plane0 = i1 (w 2^16), plane1 = i2 (2^8), plane2 = i3 (1)
__device__ __align__(16) int8_t gA_pl[3][(size_t)(MAX_N + 128) * 128];
__device__ __align__(16) int8_t gB_pl[3][1024 * 128];

// ---------------------------------------------------------------------------
__global__ void rownorm_kernel(const float* __restrict__ X, int n, int D, int is_col) {
    int warp = (blockIdx.x * blockDim.x + threadIdx.x) >> 5;
    int lane = threadIdx.x & 31;
    if (warp >= n) return;
    const float* row = X + (size_t)warp * D;
    float s = 0.f;
    for (int k = lane; k < D; k += 32) { float v = row[k]; s += v * v; }
    #pragma unroll
    for (int o = 16; o; o >>= 1) s += __shfl_xor_sync(0xFFFFFFFFu, s, o);
    if (lane == 0) { if (is_col) g_cn[warp] = s; else g_rn[warp] = s; }
}

// Fused: node-table copy + winner-table clear.
__global__ void copy_clear_kernel(const int* __restrict__ node_cell,
                                  const float* __restrict__ node_time,
                                  float* __restrict__ out_ncell,
                                  float* __restrict__ out_ntime, int m) {
    int j = blockIdx.x * blockDim.x + threadIdx.x;
    if (j < m) {
        g_winner[j] = -1;
        if (out_ncell) out_ncell[j] = (float)node_cell[j];
        if (out_ntime) out_ntime[j] = node_time[j];
    }
}

__global__ void winner_kernel(const int* __restrict__ nodes, int n, int m) {
    int i = blockIdx.x * blockDim.x + threadIdx.x;
    if (i >= n) return;
    int nd = nodes[i];
    if (nd >= 0 && nd < m) atomicMax(&g_winner[nd], i);
}

// Quantize fp32 -> 3 balanced int8 limbs of I = round(x * 2^20).
__global__ void quant_kernel(const float* __restrict__ X,
                             int8_t* __restrict__ p1, int8_t* __restrict__ p2,
                             int8_t* __restrict__ p3, int total4) {
    int i = blockIdx.x * blockDim.x + threadIdx.x;   // one per 4 elements
    if (i >= total4) return;
    float4 v = ((const float4*)X)[i];
    uint32_t w1 = 0, w2 = 0, w3 = 0;
    #pragma unroll
    for (int j = 0; j < 4; j++) {
        float x = (&v.x)[j];
        int I  = __float2int_rn(x * 1048576.0f);     // 2^20
        int i3 = ((I + 128) & 255) - 128;  int Ip = (I - i3) >> 8;
        int i2 = ((Ip + 128) & 255) - 128; int i1 = (Ip - i2) >> 8;
        w1 |= (uint32_t)(i1 & 255) << (8 * j);
        w2 |= (uint32_t)(i2 & 255) << (8 * j);
        w3 |= (uint32_t)(i3 & 255) << (8 * j);
    }
    ((uint32_t*)p1)[i] = w1;
    ((uint32_t*)p2)[i] = w2;
    ((uint32_t*)p3)[i] = w3;
}

// ---------------------------------------------------------------------------
// INT8 IMMA distance GEMM. CTA tile 128x128, 8 warps (2M x 4N), warp 64x32.
#define BM 128
#define BN 128
#define RS   144               // smem row stride bytes (128 data + 16 pad)
#define PSTR (128 * RS)        // one plane tile
#define GSMEM (6 * PSTR + BM * 4 * 8)

__device__ __forceinline__ void imma(int* c, const uint32_t* a, const uint32_t* b) {
    asm volatile(
        "mma.sync.aligned.m16n8k32.row.col.s32.s8.s8.s32 "
        "{%0,%1,%2,%3}, {%4,%5,%6,%7}, {%8,%9}, {%0,%1,%2,%3};\n"
        : "+r"(c[0]), "+r"(c[1]), "+r"(c[2]), "+r"(c[3])
        : "r"(a[0]), "r"(a[1]), "r"(a[2]), "r"(a[3]), "r"(b[0]), "r"(b[1]));
}

// One weighted pass: PASS=0 -> (A0,B0); 1 -> (A0,B1)+(A1,B0);
//                    2 -> (A1,B1)+(A0,B2)+(A2,B0).
template <int PASS>
__device__ __forceinline__ void run_pass(const uint8_t* __restrict__ Asm,
                                         const uint8_t* __restrict__ Bsm,
                                         int aRow0, int nCol0, int q,
                                         float w, float f[4][4][4]) {
    int acc[4][4][4];
    #pragma unroll
    for (int mt = 0; mt < 4; mt++)
        #pragma unroll
        for (int nt = 0; nt < 4; nt++)
            #pragma unroll
            for (int r = 0; r < 4; r++) acc[mt][nt][r] = 0;

    #pragma unroll
    for (int kc = 0; kc < 4; kc++) {
        const int kb = kc * 32 + 4 * q;
        uint32_t aF[PASS + 1][4][4];
        #pragma unroll
        for (int p = 0; p <= PASS; p++)
            #pragma unroll
            for (int mt = 0; mt < 4; mt++) {
                const uint8_t* base = Asm + p * PSTR + (aRow0 + mt * 16) * RS + kb;
                aF[p][mt][0] = *(const uint32_t*)(base);
                aF[p][mt][1] = *(const uint32_t*)(base + 8 * RS);
                aF[p][mt][2] = *(const uint32_t*)(base + 16);
                aF[p][mt][3] = *(const uint32_t*)(base + 8 * RS + 16);
            }
        #pragma unroll
        for (int nt = 0; nt < 4; nt++) {
            uint32_t bF[PASS + 1][2];
            #pragma unroll
            for (int p = 0; p <= PASS; p++) {
                const uint8_t* base = Bsm + p * PSTR + (nCol0 + nt * 8) * RS + kb;
                bF[p][0] = *(const uint32_t*)(base);
                bF[p][1] = *(const uint32_t*)(base + 16);
            }
            #pragma unroll
            for (int mt = 0; mt < 4; mt++) {
                if (PASS == 0) {
                    imma(acc[mt][nt], aF[0][mt], bF[0]);
                } else if (PASS == 1) {
                    imma(acc[mt][nt], aF[0][mt], bF[1]);
                    imma(acc[mt][nt], aF[1][mt], bF[0]);
                } else {
                    imma(acc[mt][nt], aF[1][mt], bF[1]);
                    imma(acc[mt][nt], aF[0][mt], bF[2]);
                    imma(acc[mt][nt], aF[2][mt], bF[0]);
                }
            }
        }
    }
    #pragma unroll
    for (int mt = 0; mt < 4; mt++)
        #pragma unroll
        for (int nt = 0; nt < 4; nt++)
            #pragma unroll
            for (int r = 0; r < 4; r++)
                f[mt][nt][r] += w * (float)acc[mt][nt][r];
}

__global__ __launch_bounds__(256)
void gemm_dist_i8(const int8_t* __restrict__ A0, const int8_t* __restrict__ A1,
                  const int8_t* __restrict__ A2, const int8_t* __restrict__ B0,
                  const int8_t* __restrict__ B1, const int8_t* __restrict__ B2,
                  float* __restrict__ out, int N, int C) {
    extern __shared__ uint8_t smemb[];
    uint8_t* Asm = smemb;                 // 3 planes
    uint8_t* Bsm = smemb + 3 * PSTR;      // 3 planes
    unsigned long long* best_sh = (unsigned long long*)(smemb + 6 * PSTR);

    const int tid   = threadIdx.x;
    const int lane  = tid & 31;
    const int warp  = tid >> 5;
    const int warpM = warp >> 2;
    const int warpN = warp & 3;
    const int brow  = blockIdx.y * BM;
    const int bcol  = blockIdx.x * BN;
    const int g     = lane >> 2;
    const int q     = lane & 3;

    // Loader: 6 planes x 16 KB; each thread 4 int4 per plane.
    const int8_t* Apl[3] = { A0, A1, A2 };
    const int8_t* Bpl[3] = { B0, B1, B2 };
    #pragma unroll
    for (int p = 0; p < 3; p++) {
        #pragma unroll
        for (int i = 0; i < 4; i++) {
            int j   = tid + i * 256;         // 0..1023
            int row = j >> 3;
            int kb  = (j & 7) * 16;
            *(int4*)(Asm + p * PSTR + row * RS + kb) =
                *(const int4*)(Apl[p] + (size_t)(brow + row) * 128 + kb);
            *(int4*)(Bsm + p * PSTR + row * RS + kb) =
                *(const int4*)(Bpl[p] + (size_t)(bcol + row) * 128 + kb);
        }
    }
    __syncthreads();

    const int aRow0 = warpM * 64 + g;
    const int nCol0 = warpN * 32 + g;
    float f[4][4][4];
    #pragma unroll
    for (int mt = 0; mt < 4; mt++)
        #pragma unroll
        for (int nt = 0; nt < 4; nt++)
            #pragma unroll
            for (int r = 0; r < 4; r++) f[mt][nt][r] = 0.f;

    run_pass<0>(Asm, Bsm, aRow0, nCol0, q, 0x1p-8f,  f);
    run_pass<1>(Asm, Bsm, aRow0, nCol0, q, 0x1p-16f, f);
    run_pass<2>(Asm, Bsm, aRow0, nCol0, q, 0x1p-24f, f);

    // Epilogue: dist = sqrt(max(rn + cn - 2*dot, 0)); write + per-row argmin.
    float cn0[4], cn1[4];
    #pragma unroll
    for (int nt = 0; nt < 4; nt++) {
        int col = bcol + warpN * 32 + nt * 8 + q * 2;
        cn0[nt] = g_cn[col];
        cn1[nt] = g_cn[col + 1];
    }

    #pragma unroll
    for (int mt = 0; mt < 4; mt++) {
        #pragma unroll
        for (int half = 0; half < 2; half++) {
            int rloc = warpM * 64 + mt * 16 + g + half * 8;
            int grow = brow + rloc;
            bool rowok = (grow < N);
            float rn = rowok ? g_rn[grow] : 0.f;
            unsigned long long best = ~0ull;
            #pragma unroll
            for (int nt = 0; nt < 4; nt++) {
                int col = bcol + warpN * 32 + nt * 8 + q * 2;
                float d0 = sqrtf(fmaxf(rn + cn0[nt] - 2.0f * f[mt][nt][half * 2 + 0], 0.f));
                float d1 = sqrtf(fmaxf(rn + cn1[nt] - 2.0f * f[mt][nt][half * 2 + 1], 0.f));
                unsigned long long k0 =
                    ((unsigned long long)__float_as_uint(d0) << 32) | (unsigned)col;
                unsigned long long k1 =
                    ((unsigned long long)__float_as_uint(d1) << 32) | (unsigned)(col + 1);
                best = (k0 < best) ? k0 : best;
                best = (k1 < best) ? k1 : best;
                if (rowok && out) {
                    float2 dv = make_float2(d0, d1);
                    *(float2*)(out + (size_t)grow * C + col) = dv;
                }
            }
            #pragma unroll
            for (int o = 1; o <= 2; o <<= 1) {
                unsigned long long other = __shfl_xor_sync(0xFFFFFFFFu, best, o);
                best = (other < best) ? other : best;
            }
            if (q == 0) best_sh[rloc * 4 + warpN] = best;
        }
    }
    __syncthreads();

    if (tid < BM) {
        int grow = brow + tid;
        if (grow < N) {
            unsigned long long best = best_sh[tid * 4];
            #pragma unroll
            for (int j = 1; j < 4; j++) {
                unsigned long long k = best_sh[tid * 4 + j];
                best = (k < best) ? k : best;
            }
            g_cand[(size_t)grow * NCB + blockIdx.x] = best;
        }
    }
}

// ---------------------------------------------------------------------------
__global__ void scatter_kernel(const int* __restrict__ nodes,
                               const float* __restrict__ times,
                               float* __restrict__ out_cells,
                               float* __restrict__ out_ncell,
                               float* __restrict__ out_ntime, int n, int m) {
    int i = blockIdx.x * blockDim.x + threadIdx.x;
    if (i >= n) return;
    const unsigned long long* cand = &g_cand[(size_t)i * NCB];
    unsigned long long best = cand[0];
    #pragma unroll
    for (int cb = 1; cb < NCB; cb++) {
        unsigned long long k = cand[cb];
        best = (k < best) ? k : best;
    }
    int cell = (int)(unsigned)(best & 0xFFFFFFFFull);
    if (out_cells) out_cells[i] = (float)cell;
    int nd = nodes[i];
    if (nd >= 0 && nd < m && g_winner[nd] == i) {
        if (out_ncell) out_ncell[nd] = (float)cell;
        if (out_ntime) out_ntime[nd] = times[i];
    }
}

// ---------------------------------------------------------------------------
extern "C" void kernel_launch(void* const* d_in, const int* in_sizes, int n_in,
                              void* d_out, int out_size) {
    const float* emb       = (const float*)d_in[0];   // [N, D]
    const float* mmap      = (const float*)d_in[1];   // [C, D]
    const int*   nodes     = (const int*)d_in[2];     // [N]
    const float* times     = (const float*)d_in[3];   // [N]
    const int*   node_cell = (const int*)d_in[4];     // [NUM_NODES]
    const float* node_time = (const float*)d_in[5];   // [NUM_NODES]

    const int D = 128;
    const int N = in_sizes[0] / D;       // 100000
    const int C = in_sizes[1] / D;       // 1024
    const int M = in_sizes[4];           // 1000000

    size_t have = (size_t)out_size;
    size_t nc = (size_t)N * C;
    float* base = (float*)d_out;
    float* out_dist  = (have >= nc) ? base : nullptr;
    float* out_cells = (have >= nc + (size_t)N) ? base + nc : nullptr;
    float* out_ncell = (have >= nc + N + (size_t)M) ? base + nc + N : nullptr;
    float* out_ntime = (have >= nc + N + 2ull * M) ? base + nc + N + M : nullptr;

    // Resolve device-global plane pointers (host-side, capture-safe).
    static int8_t* hA[3] = {nullptr, nullptr, nullptr};
    static int8_t* hB[3] = {nullptr, nullptr, nullptr};
    if (!hA[0]) {
        int8_t (*pa)[(size_t)(MAX_N + 128) * 128];
        int8_t (*pb)[1024 * 128];
        cudaGetSymbolAddress((void**)&pa, gA_pl);
        cudaGetSymbolAddress((void**)&pb, gB_pl);
        for (int p = 0; p < 3; p++) { hA[p] = pa[p]; hB[p] = pb[p]; }
    }

    rownorm_kernel<<<(N * 32 + 255) / 256, 256>>>(emb, N, D, 0);
    rownorm_kernel<<<(C * 32 + 255) / 256, 256>>>(mmap, C, D, 1);
    copy_clear_kernel<<<(M + 255) / 256, 256>>>(node_cell, node_time,
                                                out_ncell, out_ntime, M);
    winner_kernel<<<(N + 255) / 256, 256>>>(nodes, N, M);

    int a4 = N * D / 4, b4 = C * D / 4;
    quant_kernel<<<(a4 + 255) / 256, 256>>>(emb, hA[0], hA[1], hA[2], a4);
    quant_kernel<<<(b4 + 255) / 256, 256>>>(mmap, hB[0], hB[1], hB[2], b4);

    {
        cudaFuncSetAttribute(gemm_dist_i8,
                             cudaFuncAttributeMaxDynamicSharedMemorySize, GSMEM);
        dim3 grid(C / BN, (N + BM - 1) / BM);
        gemm_dist_i8<<<grid, 256, GSMEM>>>(hA[0], hA[1], hA[2],
                                           hB[0], hB[1], hB[2],
                                           out_dist, N, C);
    }
    scatter_kernel<<<(N + 255) / 256, 256>>>(nodes, times, out_cells,
                                             out_ncell, out_ntime, N, M);
}

// round 15
// speedup vs baseline: 3.2105x; 3.2105x over previous
#include <cuda_runtime.h>
#include <cuda_fp16.h>
#include <math.h>
#include <stdint.h>

// Problem constants: N=100000, D=128, C=1024, NUM_NODES=1e6.
#define MAX_N     100000
#define MAX_NODES 1000000
#define NCB       8            // C / BN column blocks

// Device scratch (no allocs allowed). NO 64-bit atomics (sm_103a trap).
__device__ unsigned long long g_cand[(size_t)(MAX_N + 128) * NCB];
__device__ int   g_winner[MAX_NODES];
__device__ float g_rn[MAX_N];
__device__ float g_cn[2048];

// ---------------------------------------------------------------------------
__global__ void rownorm_kernel(const float* __restrict__ X, int n, int D, int is_col) {
    int warp = (blockIdx.x * blockDim.x + threadIdx.x) >> 5;
    int lane = threadIdx.x & 31;
    if (warp >= n) return;
    const float* row = X + (size_t)warp * D;
    float s = 0.f;
    for (int k = lane; k < D; k += 32) { float v = row[k]; s += v * v; }
    #pragma unroll
    for (int o = 16; o; o >>= 1) s += __shfl_xor_sync(0xFFFFFFFFu, s, o);
    if (lane == 0) { if (is_col) g_cn[warp] = s; else g_rn[warp] = s; }
}

// Fused: node-table copy + winner-table clear.
__global__ void copy_clear_kernel(const int* __restrict__ node_cell,
                                  const float* __restrict__ node_time,
                                  float* __restrict__ out_ncell,
                                  float* __restrict__ out_ntime, int m) {
    int j = blockIdx.x * blockDim.x + threadIdx.x;
    if (j < m) {
        g_winner[j] = -1;
        if (out_ncell) out_ncell[j] = (float)node_cell[j];
        if (out_ntime) out_ntime[j] = node_time[j];
    }
}

__global__ void winner_kernel(const int* __restrict__ nodes, int n, int m) {
    int i = blockIdx.x * blockDim.x + threadIdx.x;
    if (i >= n) return;
    int nd = nodes[i];
    if (nd >= 0 && nd < m) atomicMax(&g_winner[nd], i);
}

// ---------------------------------------------------------------------------
// fp16 3-limb tensor-core distance GEMM (hh + hl + lh), fp32 accumulate.
// Block tile 128x128, 8 warps in 2(M) x 4(N), warp 64x32, m16n8k16.
#define BM 128
#define BN 128
#define BK 32
#define SROW 36                // 36-float row stride: 16B-aligned, ok banks

// Load 2 consecutive floats; emit packed half2 hi and half2 lo (residual).
__device__ __forceinline__ void split2(const float* __restrict__ p,
                                       uint32_t& h2, uint32_t& l2) {
    float x = p[0], y = p[1];
    __half hx = __float2half_rn(x);
    __half hy = __float2half_rn(y);
    float lx = x - __half2float(hx);
    float ly = y - __half2float(hy);
    __half2 H = __halves2half2(hx, hy);
    __half2 L = __floats2half2_rn(lx, ly);
    h2 = *(uint32_t*)&H;
    l2 = *(uint32_t*)&L;
}

__device__ __forceinline__ void mma_f16(float* c, const uint32_t* a, const uint32_t* b) {
    asm volatile(
        "mma.sync.aligned.m16n8k16.row.col.f32.f16.f16.f32 "
        "{%0,%1,%2,%3}, {%4,%5,%6,%7}, {%8,%9}, {%0,%1,%2,%3};\n"
        : "+f"(c[0]), "+f"(c[1]), "+f"(c[2]), "+f"(c[3])
        : "r"(a[0]), "r"(a[1]), "r"(a[2]), "r"(a[3]), "r"(b[0]), "r"(b[1]));
}

__global__ __launch_bounds__(256, 2)
void gemm_dist_f16(const float* __restrict__ A,   // [N, 128]
                   const float* __restrict__ B,   // [1024, 128]
                   float* __restrict__ out,       // [N, 1024] (may be null)
                   int N, int C, int D) {
    __shared__ float As[BM][SROW];
    __shared__ float Bs[BN][SROW];
    __shared__ unsigned long long best_sh[BM][4];

    const int tid   = threadIdx.x;
    const int lane  = tid & 31;
    const int warp  = tid >> 5;
    const int warpM = warp >> 2;       // 0..1
    const int warpN = warp & 3;        // 0..3
    const int brow  = blockIdx.y * BM;
    const int bcol  = blockIdx.x * BN;
    const int g     = lane >> 2;       // groupID 0..7
    const int q     = lane & 3;        // quad lane 0..3

    float acc[4][4][4];                // [mtile][ntile][reg]
    #pragma unroll
    for (int mt = 0; mt < 4; mt++)
        #pragma unroll
        for (int nt = 0; nt < 4; nt++)
            #pragma unroll
            for (int r = 0; r < 4; r++) acc[mt][nt][r] = 0.f;

    // Loader: 256 threads; each 4 float4 per matrix (rows tid>>3 (+32i)).
    const int lrow = tid >> 3;          // 0..31
    const int lk4  = (tid & 7) * 4;     // 0..28

    for (int kc = 0; kc < 4; kc++) {
        const int k0 = kc * BK;
        float4 av[4], bv[4];
        #pragma unroll
        for (int i = 0; i < 4; i++) {
            int ar = min(brow + lrow + i * 32, N - 1);
            av[i] = *(const float4*)(A + (size_t)ar * D + k0 + lk4);
            bv[i] = *(const float4*)(B + (size_t)(bcol + lrow + i * 32) * D + k0 + lk4);
        }
        __syncthreads();
        #pragma unroll
        for (int i = 0; i < 4; i++) {
            *(float4*)&As[lrow + i * 32][lk4] = av[i];
            *(float4*)&Bs[lrow + i * 32][lk4] = bv[i];
        }
        __syncthreads();

        #pragma unroll
        for (int kk = 0; kk < 2; kk++) {        // two k16 steps per 32-K chunk
            const int kb = kk * 16 + 2 * q;
            uint32_t ah[4][4], al[4][4];
            #pragma unroll
            for (int mt = 0; mt < 4; mt++) {
                const float* pr = &As[warpM * 64 + mt * 16 + g][kb];
                split2(pr,                ah[mt][0], al[mt][0]);
                split2(pr + 8 * SROW,     ah[mt][1], al[mt][1]);
                split2(pr + 8,            ah[mt][2], al[mt][2]);
                split2(pr + 8 * SROW + 8, ah[mt][3], al[mt][3]);
            }
            #pragma unroll
            for (int nt = 0; nt < 4; nt++) {
                const float* pb = &Bs[warpN * 32 + nt * 8 + g][kb];
                uint32_t bh[2], bl[2];
                split2(pb,     bh[0], bl[0]);
                split2(pb + 8, bh[1], bl[1]);
                #pragma unroll
                for (int mt = 0; mt < 4; mt++) {
                    mma_f16(acc[mt][nt], ah[mt], bh);
                    mma_f16(acc[mt][nt], ah[mt], bl);
                    mma_f16(acc[mt][nt], al[mt], bh);
                }
            }
        }
    }

    // Epilogue: dist = sqrt(max(rn + cn - 2*dot, 0)); write + per-row argmin.
    float cn0[4], cn1[4];
    #pragma unroll
    for (int nt = 0; nt < 4; nt++) {
        int col = bcol + warpN * 32 + nt * 8 + q * 2;
        cn0[nt] = g_cn[col];
        cn1[nt] = g_cn[col + 1];
    }

    #pragma unroll
    for (int mt = 0; mt < 4; mt++) {
        #pragma unroll
        for (int half = 0; half < 2; half++) {
            int rloc = warpM * 64 + mt * 16 + g + half * 8;
            int grow = brow + rloc;
            bool rowok = (grow < N);
            float rn = rowok ? g_rn[grow] : 0.f;
            unsigned long long best = ~0ull;
            #pragma unroll
            for (int nt = 0; nt < 4; nt++) {
                int col = bcol + warpN * 32 + nt * 8 + q * 2;
                float d0 = sqrtf(fmaxf(rn + cn0[nt] - 2.0f * acc[mt][nt][half * 2 + 0], 0.f));
                float d1 = sqrtf(fmaxf(rn + cn1[nt] - 2.0f * acc[mt][nt][half * 2 + 1], 0.f));
                unsigned long long k0 =
                    ((unsigned long long)__float_as_uint(d0) << 32) | (unsigned)col;
                unsigned long long k1 =
                    ((unsigned long long)__float_as_uint(d1) << 32) | (unsigned)(col + 1);
                best = (k0 < best) ? k0 : best;
                best = (k1 < best) ? k1 : best;
                if (rowok && out) {
                    float2 dv = make_float2(d0, d1);
                    *(float2*)(out + (size_t)grow * C + col) = dv;
                }
            }
            #pragma unroll
            for (int o = 1; o <= 2; o <<= 1) {
                unsigned long long other = __shfl_xor_sync(0xFFFFFFFFu, best, o);
                best = (other < best) ? other : best;
            }
            if (q == 0) best_sh[rloc][warpN] = best;
        }
    }
    __syncthreads();

    if (tid < BM) {
        int grow = brow + tid;
        if (grow < N) {
            unsigned long long best = best_sh[tid][0];
            #pragma unroll
            for (int j = 1; j < 4; j++) {
                unsigned long long k = best_sh[tid][j];
                best = (k < best) ? k : best;
            }
            g_cand[(size_t)grow * NCB + blockIdx.x] = best;
        }
    }
}

// ---------------------------------------------------------------------------
__global__ void scatter_kernel(const int* __restrict__ nodes,
                               const float* __restrict__ times,
                               float* __restrict__ out_cells,
                               float* __restrict__ out_ncell,
                               float* __restrict__ out_ntime, int n, int m) {
    int i = blockIdx.x * blockDim.x + threadIdx.x;
    if (i >= n) return;
    const unsigned long long* cand = &g_cand[(size_t)i * NCB];
    unsigned long long best = cand[0];
    #pragma unroll
    for (int cb = 1; cb < NCB; cb++) {
        unsigned long long k = cand[cb];
        best = (k < best) ? k : best;
    }
    int cell = (int)(unsigned)(best & 0xFFFFFFFFull);
    if (out_cells) out_cells[i] = (float)cell;
    int nd = nodes[i];
    if (nd >= 0 && nd < m && g_winner[nd] == i) {
        if (out_ncell) out_ncell[nd] = (float)cell;
        if (out_ntime) out_ntime[nd] = times[i];
    }
}

// ---------------------------------------------------------------------------
extern "C" void kernel_launch(void* const* d_in, const int* in_sizes, int n_in,
                              void* d_out, int out_size) {
    const float* emb       = (const float*)d_in[0];   // [N, D]
    const float* mmap      = (const float*)d_in[1];   // [C, D]
    const int*   nodes     = (const int*)d_in[2];     // [N]
    const float* times     = (const float*)d_in[3];   // [N]
    const int*   node_cell = (const int*)d_in[4];     // [NUM_NODES]
    const float* node_time = (const float*)d_in[5];   // [NUM_NODES]

    const int D = 128;
    const int N = in_sizes[0] / D;       // 100000
    const int C = in_sizes[1] / D;       // 1024
    const int M = in_sizes[4];           // 1000000

    size_t have = (size_t)out_size;
    size_t nc = (size_t)N * C;
    float* base = (float*)d_out;
    float* out_dist  = (have >= nc) ? base : nullptr;
    float* out_cells = (have >= nc + (size_t)N) ? base + nc : nullptr;
    float* out_ncell = (have >= nc + N + (size_t)M) ? base + nc + N : nullptr;
    float* out_ntime = (have >= nc + N + 2ull * M) ? base + nc + N + M : nullptr;

    rownorm_kernel<<<(N * 32 + 255) / 256, 256>>>(emb, N, D, 0);
    rownorm_kernel<<<(C * 32 + 255) / 256, 256>>>(mmap, C, D, 1);
    copy_clear_kernel<<<(M + 255) / 256, 256>>>(node_cell, node_time,
                                                out_ncell, out_ntime, M);
    winner_kernel<<<(N + 255) / 256, 256>>>(nodes, N, M);
    {
        dim3 grid(C / BN, (N + BM - 1) / BM);
        gemm_dist_f16<<<grid, 256>>>(emb, mmap, out_dist, N, C, D);
    }
    scatter_kernel<<<(N + 255) / 256, 256>>>(nodes, times, out_cells,
                                             out_ncell, out_ntime, N, M);
}